// round 13
// baseline (speedup 1.0000x reference)
#include <cuda_runtime.h>
#include <cuda_fp16.h>
#include <cstdint>
#include <math.h>

#define B_   16
#define LT   512
#define LI   576
#define TD   768
#define ID   1024
#define HID  2048
#define NH   8
#define HD   256
#define FFD  128

typedef __half fp16;

// ---- scratch (device globals) ----
__device__ fp16 g_t1[B_ * LT * TD];
__device__ fp16 g_i1[B_ * LI * ID];
__device__ fp16 g_wq[HID * TD];
__device__ fp16 g_wk[HID * ID];
__device__ fp16 g_wv[HID * ID];
__device__ fp16 g_wr[TD * HID];
__device__ fp16 g_w1[FFD * TD];
__device__ fp16 g_w2[TD * FFD];
__device__ fp16 g_Q1[B_ * LT * HID];
__device__ fp16 g_K1[B_ * LI * HID];
__device__ fp16 g_V1[B_ * LI * HID];
__device__ fp16 g_X1[B_ * LT * HID];
__device__ fp16 g_O1[B_ * LT * TD];
__device__ fp16 g_H1[B_ * LT * FFD];
__device__ float g_O[B_ * LT * TD];
__device__ float g_F[B_ * LT * TD];

// ===========================================================================
// helpers
// ===========================================================================
__device__ __forceinline__ void hmma2(float* c, const uint32_t* a, uint32_t b0, uint32_t b1)
{
    asm volatile(
        "mma.sync.aligned.m16n8k16.row.col.f32.f16.f16.f32 "
        "{%0,%1,%2,%3}, {%4,%5,%6,%7}, {%8,%9}, {%0,%1,%2,%3};"
        : "+f"(c[0]), "+f"(c[1]), "+f"(c[2]), "+f"(c[3])
        : "r"(a[0]), "r"(a[1]), "r"(a[2]), "r"(a[3]), "r"(b0), "r"(b1));
}
__device__ __forceinline__ void ldsm4(uint32_t* r, uint32_t addr)
{
    asm volatile("ldmatrix.sync.aligned.m8n8.x4.shared.b16 {%0,%1,%2,%3}, [%4];"
                 : "=r"(r[0]), "=r"(r[1]), "=r"(r[2]), "=r"(r[3]) : "r"(addr));
}
__device__ __forceinline__ void ldsm4t(uint32_t* r, uint32_t addr)
{
    asm volatile("ldmatrix.sync.aligned.m8n8.x4.trans.shared.b16 {%0,%1,%2,%3}, [%4];"
                 : "=r"(r[0]), "=r"(r[1]), "=r"(r[2]), "=r"(r[3]) : "r"(addr));
}
__device__ __forceinline__ uint32_t smem_u32(const void* p) {
    uint32_t a;
    asm("{ .reg .u64 t; cvta.to.shared.u64 t, %1; cvt.u32.u64 %0, t; }" : "=r"(a) : "l"(p));
    return a;
}
__device__ __forceinline__ uint32_t pack_f16x2(float x0, float x1)
{
    __half2 h = __floats2half2_rn(x0, x1);
    return *(uint32_t*)&h;
}
#define CP16(s, g) \
    asm volatile("cp.async.cg.shared.global [%0], [%1], 16;" :: "r"(s), "l"(g) : "memory")
#define CPCOMMIT() asm volatile("cp.async.commit_group;" ::: "memory")
#define CPWAIT(n)  asm volatile("cp.async.wait_group %0;" :: "n"(n) : "memory")

// ===========================================================================
// Fused pre-pass (one launch): activation fp32->fp16 + 6 weight transposes.
// ===========================================================================
#define PREP_GRID 22720

__device__ __forceinline__ void cvt_seg(const float* X, fp16* H, int loc)
{
    const int i = (loc * 256 + threadIdx.x) * 4;
    float4 v = *(const float4*)&X[i];
    *(uint32_t*)&H[i]     = pack_f16x2(v.x, v.y);
    *(uint32_t*)&H[i + 2] = pack_f16x2(v.z, v.w);
}
__device__ __forceinline__ void tr_seg(const float* W, fp16* T, int K, int N, int loc)
{
    __shared__ float t[32][33];
    const int nt = loc % (N >> 5), kt = loc / (N >> 5);
    const int n0 = nt * 32, k0 = kt * 32;
    const int tx = threadIdx.x & 31, ty4 = (threadIdx.x >> 5) * 4;
#pragma unroll
    for (int i = 0; i < 4; i++)
        t[ty4 + i][tx] = W[(size_t)(k0 + ty4 + i) * N + n0 + tx];
    __syncthreads();
#pragma unroll
    for (int i = 0; i < 4; i++)
        T[(size_t)(n0 + ty4 + i) * K + k0 + tx] = __float2half_rn(t[tx][ty4 + i]);
}

__global__ __launch_bounds__(256)
void prep(const float* __restrict__ text, const float* __restrict__ image,
          const float* __restrict__ wq, const float* __restrict__ wk,
          const float* __restrict__ wv, const float* __restrict__ wr,
          const float* __restrict__ w1, const float* __restrict__ w2,
          fp16* t1, fp16* i1, fp16* pwq, fp16* pwk, fp16* pwv,
          fp16* pwr, fp16* pw1, fp16* pw2)
{
    const int g = blockIdx.x;
    if      (g < 6144)  cvt_seg(text,  t1, g);
    else if (g < 15360) cvt_seg(image, i1, g - 6144);
    else if (g < 16896) tr_seg(wq, pwq, TD,  HID, g - 15360);
    else if (g < 18944) tr_seg(wk, pwk, ID,  HID, g - 16896);
    else if (g < 20992) tr_seg(wv, pwv, ID,  HID, g - 18944);
    else if (g < 22528) tr_seg(wr, pwr, HID, TD,  g - 20992);
    else if (g < 22624) tr_seg(w1, pw1, TD,  FFD, g - 22528);
    else                tr_seg(w2, pw2, FFD, TD,  g - 22624);
}

// ===========================================================================
// fp16 GEMM body: C = A[M,K] @ B1[N,K]^T + bias
// 128x128 block, BK=64, 2-stage cp.async double-buffer, 2 CTAs/SM.
// Requires K % 64 == 0 (all: 768, 1024, 2048, 128).
// ===========================================================================
#define KPAD 72                     // 64 + 8 halves (144 B rows, ldsm-clean)
#define CB   (128 * KPAD * 2)       // 18432 B per operand tile
#define STGB (2 * CB)               // 36864 B per stage
#define GSMEM_BYTES (2 * STGB)      // 73728

__device__ __forceinline__ void gemm_body(
    const fp16* __restrict__ A, const fp16* __restrict__ B1,
    const float* __restrict__ bias,
    float* Cf, fp16* Ch,
    int N, int Kd, int relu, float oscale,
    int bm, int bn, uint32_t sbase)
{
    const int tid  = threadIdx.x;
    const int wid  = tid >> 5;
    const int lane = tid & 31;
    const int wm = (wid >> 2) * 64;
    const int wn = (wid & 3) * 32;
    const int NC = Kd >> 6;

    float acc[4][4][4];
#pragma unroll
    for (int i = 0; i < 4; i++)
#pragma unroll
        for (int j = 0; j < 4; j++)
#pragma unroll
            for (int l = 0; l < 4; l++) acc[i][j][l] = 0.0f;

    // loader: 64 k-halves/row, thread covers 8-half segment; rows l_row+{0,32,64,96}
    const int l_row = tid >> 3;          // 0..31
    const int l_sg  = (tid & 7) << 3;    // 0..56

    auto issue = [&](int c) {
        const uint32_t sb = sbase + (uint32_t)((c & 1) * STGB);
        const int k0 = c << 6;
#pragma unroll
        for (int ro = 0; ro < 4; ro++) {
            const int row = l_row + ro * 32;
            const uint32_t so = (uint32_t)((row * KPAD + l_sg) * 2);
            CP16(sb + so,      A  + (size_t)(bm + row) * Kd + k0 + l_sg);
            CP16(sb + CB + so, B1 + (size_t)(bn + row) * Kd + k0 + l_sg);
        }
        CPCOMMIT();
    };

    issue(0);

    const int lrow = lane & 15, lc8 = (lane >> 4) << 3;

    for (int c = 0; c < NC; c++) {
        if (c + 1 < NC) { issue(c + 1); CPWAIT(1); } else { CPWAIT(0); }
        __syncthreads();

        const uint32_t sb = sbase + (uint32_t)((c & 1) * STGB);
#pragma unroll
        for (int ks = 0; ks < 4; ks++) {
            const int kf = ks * 16 + lc8;
            uint32_t bh[2][4];
#pragma unroll
            for (int ng = 0; ng < 2; ng++) {
                const uint32_t ro = (uint32_t)(((wn + ng * 16 + lrow) * KPAD + kf) * 2);
                ldsm4(bh[ng], sb + CB + ro);
            }
#pragma unroll
            for (int mt = 0; mt < 4; mt++) {
                uint32_t ah[4];
                const uint32_t ro = (uint32_t)(((wm + mt * 16 + lrow) * KPAD + kf) * 2);
                ldsm4(ah, sb + ro);
#pragma unroll
                for (int ng = 0; ng < 2; ng++)
#pragma unroll
                    for (int j = 0; j < 2; j++)
                        hmma2(acc[mt][ng * 2 + j], ah, bh[ng][j], bh[ng][j + 2]);
            }
        }
        __syncthreads();
    }

    const int g = lane >> 2, t2 = (lane & 3) * 2;
#pragma unroll
    for (int mt = 0; mt < 4; mt++) {
        const int r0 = bm + wm + mt * 16 + g;
#pragma unroll
        for (int nt = 0; nt < 4; nt++) {
            const int cn = bn + wn + nt * 8 + t2;
            float2 v0, v1;
            v0.x = acc[mt][nt][0] + bias[cn];
            v0.y = acc[mt][nt][1] + bias[cn + 1];
            v1.x = acc[mt][nt][2] + bias[cn];
            v1.y = acc[mt][nt][3] + bias[cn + 1];
            if (relu) {
                v0.x = fmaxf(v0.x, 0.0f); v0.y = fmaxf(v0.y, 0.0f);
                v1.x = fmaxf(v1.x, 0.0f); v1.y = fmaxf(v1.y, 0.0f);
            }
            v0.x *= oscale; v0.y *= oscale; v1.x *= oscale; v1.y *= oscale;
            if (Cf) {
                *(float2*)&Cf[(size_t)r0 * N + cn]       = v0;
                *(float2*)&Cf[(size_t)(r0 + 8) * N + cn] = v1;
            }
            if (Ch) {
                *(uint32_t*)&Ch[(size_t)r0 * N + cn]       = pack_f16x2(v0.x, v0.y);
                *(uint32_t*)&Ch[(size_t)(r0 + 8) * N + cn] = pack_f16x2(v1.x, v1.y);
            }
        }
    }
}

__global__ __launch_bounds__(256, 2)
void gemm_f16(const fp16* __restrict__ A, const fp16* __restrict__ B1,
              const float* __restrict__ bias,
              float* Cf, fp16* Ch, int N, int Kd, int relu, float oscale)
{
    extern __shared__ char smc[];
    gemm_body(A, B1, bias, Cf, Ch, N, Kd, relu, oscale,
              blockIdx.y * 128, blockIdx.x * 128, smem_u32(smc));
}

// Fused Q/K/V projections: one launch, 3328 CTAs.
__global__ __launch_bounds__(256, 2)
void qkv_f16(const fp16* __restrict__ t1, const fp16* __restrict__ i1,
             const fp16* __restrict__ wq, const fp16* __restrict__ wk,
             const fp16* __restrict__ wv,
             const float* __restrict__ bq, const float* __restrict__ bk,
             const float* __restrict__ bv,
             fp16* __restrict__ Q1, fp16* __restrict__ K1, fp16* __restrict__ V1)
{
    extern __shared__ char smc[];
    const int gid = blockIdx.x;
    const fp16 *A, *Bw;
    const float* bias;
    fp16* C;
    int Kd, loc;
    float osc;
    if (gid < 1024)      { loc = gid;        A = t1; Bw = wq; bias = bq; C = Q1; Kd = TD; osc = 0.0625f; }
    else if (gid < 2176) { loc = gid - 1024; A = i1; Bw = wk; bias = bk; C = K1; Kd = ID; osc = 1.0f; }
    else                 { loc = gid - 2176; A = i1; Bw = wv; bias = bv; C = V1; Kd = ID; osc = 1.0f; }
    const int bn = (loc & 15) * 128;
    const int bm = (loc >> 4) * 128;
    gemm_body(A, Bw, bias, nullptr, C, HID, Kd, 0, osc, bm, bn, smem_u32(smc));
}

// ===========================================================================
// fp16 flash attention (R10 config): 256 threads, q-tile 128, kv-tile 64,
// cp.async double-buffered K/V, 9 iterations.
// ===========================================================================
#define ASD 264
#define KVB (64 * ASD * 2)                       // 33792 B per K or V buffer
#define ASMEM_BYTES (128 * ASD * 2 + 4 * KVB)    // 202752

__global__ __launch_bounds__(256, 1)
void attn2(const fp16* __restrict__ Q1, const fp16* __restrict__ K1,
           const fp16* __restrict__ V1, fp16* __restrict__ X1)
{
    extern __shared__ fp16 sm2[];
    fp16* sQ = sm2;
    const uint32_t sQb = smem_u32(sm2);
    const uint32_t sK0 = sQb + 128 * ASD * 2;
    const uint32_t sV0 = sK0 + 2 * KVB;

    const int tid  = threadIdx.x;
    const int wid  = tid >> 5;
    const int lane = tid & 31;
    const int qt = blockIdx.x, h = blockIdx.y, b = blockIdx.z;
    const int qrow0  = b * LT + qt * 128;
    const int kvrow0 = b * LI;
    const int hcol   = h * HD;

#pragma unroll
    for (int i = 0; i < 16; i++) {
        const int gi = tid + i * 256;
        const int r = gi >> 5, c8 = (gi & 31) << 3;
        *(float4*)&sQ[r * ASD + c8] =
            *(const float4*)&Q1[(size_t)(qrow0 + r) * HID + hcol + c8];
    }

    const int lrow = lane & 15, lc8 = (lane >> 4) << 3;
    const uint32_t aQ = sQb + (uint32_t)(((wid * 16 + lrow) * ASD + lc8) * 2);
    const uint32_t fro = (uint32_t)((lrow * ASD + lc8) * 2);

    auto issue_kv = [&](int st) {
        const uint32_t kb = sK0 + (uint32_t)((st & 1) * KVB);
        const uint32_t vb = sV0 + (uint32_t)((st & 1) * KVB);
#pragma unroll
        for (int i = 0; i < 8; i++) {
            const int gi = tid + i * 256;
            const int r = gi >> 5, c8 = (gi & 31) << 3;
            const uint32_t so = (uint32_t)((r * ASD + c8) * 2);
            const size_t ga = (size_t)(kvrow0 + st * 64 + r) * HID + hcol + c8;
            CP16(kb + so, K1 + ga);
            CP16(vb + so, V1 + ga);
        }
        CPCOMMIT();
    };

    float o[32][4];
#pragma unroll
    for (int i = 0; i < 32; i++)
#pragma unroll
        for (int j = 0; j < 4; j++) o[i][j] = 0.0f;
    float m0 = -1e30f, m1 = -1e30f, l0 = 0.0f, l1 = 0.0f;

    issue_kv(0);

    for (int st = 0; st < 9; st++) {
        if (st + 1 < 9) { issue_kv(st + 1); CPWAIT(1); } else { CPWAIT(0); }
        __syncthreads();

        const uint32_t aK = sK0 + (uint32_t)((st & 1) * KVB) + fro;
        const uint32_t aV = sV0 + (uint32_t)((st & 1) * KVB) + fro;

        float s[8][4];
#pragma unroll
        for (int i = 0; i < 8; i++)
#pragma unroll
            for (int j = 0; j < 4; j++) s[i][j] = 0.0f;

#pragma unroll
        for (int dc = 0; dc < 16; dc++) {
            uint32_t q0[4];
            ldsm4(q0, aQ + dc * 32);
#pragma unroll
            for (int kg = 0; kg < 4; kg++) {
                uint32_t k0[4];
                ldsm4(k0, aK + (uint32_t)(kg * 16 * ASD * 2) + dc * 32);
                hmma2(s[2 * kg],     q0, k0[0], k0[2]);
                hmma2(s[2 * kg + 1], q0, k0[1], k0[3]);
            }
        }

        float rm0 = s[0][0], rm1 = s[0][2];
#pragma unroll
        for (int nt = 0; nt < 8; nt++) {
            rm0 = fmaxf(rm0, fmaxf(s[nt][0], s[nt][1]));
            rm1 = fmaxf(rm1, fmaxf(s[nt][2], s[nt][3]));
        }
        rm0 = fmaxf(rm0, __shfl_xor_sync(0xffffffffu, rm0, 1));
        rm0 = fmaxf(rm0, __shfl_xor_sync(0xffffffffu, rm0, 2));
        rm1 = fmaxf(rm1, __shfl_xor_sync(0xffffffffu, rm1, 1));
        rm1 = fmaxf(rm1, __shfl_xor_sync(0xffffffffu, rm1, 2));
        const float nm0 = fmaxf(m0, rm0), nm1 = fmaxf(m1, rm1);
        const float sc0 = __expf(m0 - nm0), sc1 = __expf(m1 - nm1);
        m0 = nm0; m1 = nm1;
        float ps0 = 0.0f, ps1 = 0.0f;
#pragma unroll
        for (int nt = 0; nt < 8; nt++) {
            s[nt][0] = __expf(s[nt][0] - nm0); ps0 += s[nt][0];
            s[nt][1] = __expf(s[nt][1] - nm0); ps0 += s[nt][1];
            s[nt][2] = __expf(s[nt][2] - nm1); ps1 += s[nt][2];
            s[nt][3] = __expf(s[nt][3] - nm1); ps1 += s[nt][3];
        }
        ps0 += __shfl_xor_sync(0xffffffffu, ps0, 1);
        ps0 += __shfl_xor_sync(0xffffffffu, ps0, 2);
        ps1 += __shfl_xor_sync(0xffffffffu, ps1, 1);
        ps1 += __shfl_xor_sync(0xffffffffu, ps1, 2);
        l0 = l0 * sc0 + ps0;
        l1 = l1 * sc1 + ps1;

#pragma unroll
        for (int nt = 0; nt < 32; nt++) {
            o[nt][0] *= sc0; o[nt][1] *= sc0;
            o[nt][2] *= sc1; o[nt][3] *= sc1;
        }

        uint32_t pa[4][4];
#pragma unroll
        for (int kc = 0; kc < 4; kc++) {
            const float* f0 = s[2 * kc];
            const float* f1 = s[2 * kc + 1];
            pa[kc][0] = pack_f16x2(f0[0], f0[1]);
            pa[kc][1] = pack_f16x2(f0[2], f0[3]);
            pa[kc][2] = pack_f16x2(f1[0], f1[1]);
            pa[kc][3] = pack_f16x2(f1[2], f1[3]);
        }

#pragma unroll
        for (int kc = 0; kc < 4; kc++) {
            const uint32_t vbase = (uint32_t)(kc * 16 * ASD * 2);
#pragma unroll
            for (int nd = 0; nd < 16; nd++) {
                uint32_t vh[4];
                ldsm4t(vh, aV + vbase + nd * 32);
                hmma2(o[2 * nd],     pa[kc], vh[0], vh[1]);
                hmma2(o[2 * nd + 1], pa[kc], vh[2], vh[3]);
            }
        }
        __syncthreads();
    }

    const float i0 = 1.0f / l0, i1 = 1.0f / l1;
    const int g = lane >> 2, t2 = (lane & 3) * 2;
    const int r0 = qrow0 + wid * 16 + g;
#pragma unroll
    for (int nt = 0; nt < 32; nt++) {
        const int col = hcol + nt * 8 + t2;
        *(uint32_t*)&X1[(size_t)r0 * HID + col] =
            pack_f16x2(o[nt][0] * i0, o[nt][1] * i0);
        *(uint32_t*)&X1[(size_t)(r0 + 8) * HID + col] =
            pack_f16x2(o[nt][2] * i1, o[nt][3] * i1);
    }
}

// ---------------------------------------------------------------------------
// Residual + LayerNorm epilogue
// ---------------------------------------------------------------------------
__device__ __forceinline__ float block_sum(float x, float* red)
{
#pragma unroll
    for (int off = 16; off > 0; off >>= 1)
        x += __shfl_xor_sync(0xffffffffu, x, off);
    const int w = threadIdx.x >> 5;
    if ((threadIdx.x & 31) == 0) red[w] = x;
    __syncthreads();
    if (threadIdx.x < 32) {
        float y = (threadIdx.x < 8) ? red[threadIdx.x] : 0.0f;
#pragma unroll
        for (int off = 4; off > 0; off >>= 1)
            y += __shfl_xor_sync(0xffffffffu, y, off);
        if (threadIdx.x == 0) red[0] = y;
    }
    __syncthreads();
    const float r = red[0];
    __syncthreads();
    return r;
}

__global__ __launch_bounds__(256)
void ffln_kernel(const float* __restrict__ OUT, const float* __restrict__ FF,
                 const float* __restrict__ gamma, const float* __restrict__ beta,
                 float* __restrict__ Y)
{
    __shared__ float red[8];
    const int r = blockIdx.x;
    const int tid = threadIdx.x;
    float v[3];
#pragma unroll
    for (int i = 0; i < 3; i++) {
        const int idx = tid + i * 256;
        v[i] = OUT[(size_t)r * TD + idx] + FF[(size_t)r * TD + idx];
    }
    const float mu = block_sum(v[0] + v[1] + v[2], red) * (1.0f / 768.0f);
    const float d0 = v[0] - mu, d1 = v[1] - mu, d2 = v[2] - mu;
    const float var = block_sum(d0 * d0 + d1 * d1 + d2 * d2, red) * (1.0f / 768.0f);
    const float rstd = rsqrtf(var + 1e-5f);
#pragma unroll
    for (int i = 0; i < 3; i++) {
        const int idx = tid + i * 256;
        Y[(size_t)r * TD + idx] = (v[i] - mu) * rstd * gamma[idx] + beta[idx];
    }
}

// ---------------------------------------------------------------------------
extern "C" void kernel_launch(void* const* d_in, const int* in_sizes, int n_in,
                              void* d_out, int out_size)
{
    const float* text  = (const float*)d_in[0];
    const float* image = (const float*)d_in[1];
    const float* wq = (const float*)d_in[2];
    const float* bq = (const float*)d_in[3];
    const float* wk = (const float*)d_in[4];
    const float* bk = (const float*)d_in[5];
    const float* wv = (const float*)d_in[6];
    const float* bv = (const float*)d_in[7];
    const float* wr = (const float*)d_in[8];
    const float* br = (const float*)d_in[9];
    const float* w1 = (const float*)d_in[10];
    const float* b1 = (const float*)d_in[11];
    const float* w2 = (const float*)d_in[12];
    const float* b2 = (const float*)d_in[13];
    const float* gamma = (const float*)d_in[14];
    const float* beta  = (const float*)d_in[15];
    float* Y = (float*)d_out;

    fp16 *t1, *i1, *pwq, *pwk, *pwv, *pwr, *pw1, *pw2;
    fp16 *Q1, *K1, *V1, *X1, *O1, *H1;
    float *O, *F;
    cudaGetSymbolAddress((void**)&t1, g_t1);
    cudaGetSymbolAddress((void**)&i1, g_i1);
    cudaGetSymbolAddress((void**)&pwq, g_wq);  cudaGetSymbolAddress((void**)&pwk, g_wk);
    cudaGetSymbolAddress((void**)&pwv, g_wv);  cudaGetSymbolAddress((void**)&pwr, g_wr);
    cudaGetSymbolAddress((void**)&pw1, g_w1);  cudaGetSymbolAddress((void**)&pw2, g_w2);
    cudaGetSymbolAddress((void**)&Q1, g_Q1);   cudaGetSymbolAddress((void**)&K1, g_K1);
    cudaGetSymbolAddress((void**)&V1, g_V1);   cudaGetSymbolAddress((void**)&X1, g_X1);
    cudaGetSymbolAddress((void**)&O1, g_O1);   cudaGetSymbolAddress((void**)&H1, g_H1);
    cudaGetSymbolAddress((void**)&O, g_O);
    cudaGetSymbolAddress((void**)&F, g_F);

    cudaFuncSetAttribute(gemm_f16, cudaFuncAttributeMaxDynamicSharedMemorySize, GSMEM_BYTES);
    cudaFuncSetAttribute(qkv_f16,  cudaFuncAttributeMaxDynamicSharedMemorySize, GSMEM_BYTES);
    cudaFuncSetAttribute(attn2, cudaFuncAttributeMaxDynamicSharedMemorySize, ASMEM_BYTES);

    // --- fused pre-pass (1 launch) ---
    prep<<<PREP_GRID, 256>>>(text, image, wq, wk, wv, wr, w1, w2,
                             t1, i1, pwq, pwk, pwv, pwr, pw1, pw2);

    // --- fused Q/K/V projections (Q scaled by 1/sqrt(256)) ---
    qkv_f16<<<3328, 256, GSMEM_BYTES>>>(t1, i1, pwq, pwk, pwv, bq, bk, bv, Q1, K1, V1);

    // --- attention ---
    attn2<<<dim3(LT / 128, NH, B_), 256, ASMEM_BYTES>>>(Q1, K1, V1, X1);

    // --- output projection + FF ---
    gemm_f16<<<dim3(TD / 128, (B_ * LT) / 128), 256, GSMEM_BYTES>>>(
        X1, pwr, br, O, O1, TD, HID, 0, 1.0f);
    gemm_f16<<<dim3(FFD / 128, (B_ * LT) / 128), 256, GSMEM_BYTES>>>(
        O1, pw1, b1, nullptr, H1, FFD, TD, 1, 1.0f);
    gemm_f16<<<dim3(TD / 128, (B_ * LT) / 128), 256, GSMEM_BYTES>>>(
        H1, pw2, b2, F, nullptr, TD, FFD, 0, 1.0f);

    // --- residual + LayerNorm ---
    ffln_kernel<<<B_ * LT, 256>>>(O, F, gamma, beta, Y);
}

// round 14
// speedup vs baseline: 1.4114x; 1.4114x over previous
#include <cuda_runtime.h>
#include <cuda_fp16.h>
#include <cstdint>
#include <math.h>

#define B_   16
#define LT   512
#define LI   576
#define TD   768
#define ID   1024
#define HID  2048
#define NH   8
#define HD   256
#define FFD  128

typedef __half fp16;

// ---- scratch (device globals) ----
__device__ fp16 g_t1[B_ * LT * TD];
__device__ fp16 g_i1[B_ * LI * ID];
__device__ fp16 g_wq[HID * TD];
__device__ fp16 g_wk[HID * ID];
__device__ fp16 g_wv[HID * ID];
__device__ fp16 g_wr[TD * HID];
__device__ fp16 g_w1[FFD * TD];
__device__ fp16 g_w2[TD * FFD];
__device__ fp16 g_Q1[B_ * LT * HID];
__device__ fp16 g_K1[B_ * LI * HID];
__device__ fp16 g_V1[B_ * LI * HID];
__device__ fp16 g_X1[B_ * LT * HID];
__device__ fp16 g_O1[B_ * LT * TD];
__device__ fp16 g_H1[B_ * LT * FFD];
__device__ float g_O[B_ * LT * TD];
__device__ float g_F[B_ * LT * TD];

// ===========================================================================
// helpers
// ===========================================================================
__device__ __forceinline__ void hmma2(float* c, const uint32_t* a, uint32_t b0, uint32_t b1)
{
    asm volatile(
        "mma.sync.aligned.m16n8k16.row.col.f32.f16.f16.f32 "
        "{%0,%1,%2,%3}, {%4,%5,%6,%7}, {%8,%9}, {%0,%1,%2,%3};"
        : "+f"(c[0]), "+f"(c[1]), "+f"(c[2]), "+f"(c[3])
        : "r"(a[0]), "r"(a[1]), "r"(a[2]), "r"(a[3]), "r"(b0), "r"(b1));
}
__device__ __forceinline__ void ldsm4(uint32_t* r, uint32_t addr)
{
    asm volatile("ldmatrix.sync.aligned.m8n8.x4.shared.b16 {%0,%1,%2,%3}, [%4];"
                 : "=r"(r[0]), "=r"(r[1]), "=r"(r[2]), "=r"(r[3]) : "r"(addr));
}
__device__ __forceinline__ void ldsm4t(uint32_t* r, uint32_t addr)
{
    asm volatile("ldmatrix.sync.aligned.m8n8.x4.trans.shared.b16 {%0,%1,%2,%3}, [%4];"
                 : "=r"(r[0]), "=r"(r[1]), "=r"(r[2]), "=r"(r[3]) : "r"(addr));
}
__device__ __forceinline__ uint32_t smem_u32(const void* p) {
    uint32_t a;
    asm("{ .reg .u64 t; cvta.to.shared.u64 t, %1; cvt.u32.u64 %0, t; }" : "=r"(a) : "l"(p));
    return a;
}
__device__ __forceinline__ uint32_t pack_f16x2(float x0, float x1)
{
    __half2 h = __floats2half2_rn(x0, x1);
    return *(uint32_t*)&h;
}
#define CP16(s, g) \
    asm volatile("cp.async.cg.shared.global [%0], [%1], 16;" :: "r"(s), "l"(g) : "memory")
#define CPCOMMIT() asm volatile("cp.async.commit_group;" ::: "memory")
#define CPWAIT(n)  asm volatile("cp.async.wait_group %0;" :: "n"(n) : "memory")

// ===========================================================================
// Fused pre-pass (one launch): activation fp32->fp16 + 6 weight transposes.
// ===========================================================================
#define PREP_GRID 22720

__device__ __forceinline__ void cvt_seg(const float* X, fp16* H, int loc)
{
    const int i = (loc * 256 + threadIdx.x) * 4;
    float4 v = *(const float4*)&X[i];
    *(uint32_t*)&H[i]     = pack_f16x2(v.x, v.y);
    *(uint32_t*)&H[i + 2] = pack_f16x2(v.z, v.w);
}
__device__ __forceinline__ void tr_seg(const float* W, fp16* T, int K, int N, int loc)
{
    __shared__ float t[32][33];
    const int nt = loc % (N >> 5), kt = loc / (N >> 5);
    const int n0 = nt * 32, k0 = kt * 32;
    const int tx = threadIdx.x & 31, ty4 = (threadIdx.x >> 5) * 4;
#pragma unroll
    for (int i = 0; i < 4; i++)
        t[ty4 + i][tx] = W[(size_t)(k0 + ty4 + i) * N + n0 + tx];
    __syncthreads();
#pragma unroll
    for (int i = 0; i < 4; i++)
        T[(size_t)(n0 + ty4 + i) * K + k0 + tx] = __float2half_rn(t[tx][ty4 + i]);
}

__global__ __launch_bounds__(256)
void prep(const float* __restrict__ text, const float* __restrict__ image,
          const float* __restrict__ wq, const float* __restrict__ wk,
          const float* __restrict__ wv, const float* __restrict__ wr,
          const float* __restrict__ w1, const float* __restrict__ w2,
          fp16* t1, fp16* i1, fp16* pwq, fp16* pwk, fp16* pwv,
          fp16* pwr, fp16* pw1, fp16* pw2)
{
    const int g = blockIdx.x;
    if      (g < 6144)  cvt_seg(text,  t1, g);
    else if (g < 15360) cvt_seg(image, i1, g - 6144);
    else if (g < 16896) tr_seg(wq, pwq, TD,  HID, g - 15360);
    else if (g < 18944) tr_seg(wk, pwk, ID,  HID, g - 16896);
    else if (g < 20992) tr_seg(wv, pwv, ID,  HID, g - 18944);
    else if (g < 22528) tr_seg(wr, pwr, HID, TD,  g - 20992);
    else if (g < 22624) tr_seg(w1, pw1, TD,  FFD, g - 22528);
    else                tr_seg(w2, pw2, FFD, TD,  g - 22624);
}

// ===========================================================================
// fp16 GEMM body (R12 config): C = A[M,K] @ B1[N,K]^T + bias
// 128x128 block, BK=32, 3-stage cp.async pipeline, 2 CTAs/SM.
// ===========================================================================
#define KPAD 40
#define CB   (128 * KPAD * 2)
#define STGB (2 * CB)
#define GSMEM_BYTES (3 * STGB)

__device__ __forceinline__ void gemm_body(
    const fp16* __restrict__ A, const fp16* __restrict__ B1,
    const float* __restrict__ bias,
    float* Cf, fp16* Ch,
    int N, int Kd, int relu, float oscale,
    int bm, int bn, uint32_t sbase)
{
    const int tid  = threadIdx.x;
    const int wid  = tid >> 5;
    const int lane = tid & 31;
    const int wm = (wid >> 2) * 64;
    const int wn = (wid & 3) * 32;
    const int NC = Kd >> 5;

    float acc[4][4][4];
#pragma unroll
    for (int i = 0; i < 4; i++)
#pragma unroll
        for (int j = 0; j < 4; j++)
#pragma unroll
            for (int l = 0; l < 4; l++) acc[i][j][l] = 0.0f;

    const int l_row = tid >> 2, l_sg = (tid & 3) << 3;
    const uint32_t l_so  = (uint32_t)((l_row * KPAD + l_sg) * 2);
    const uint32_t l_so2 = (uint32_t)(((l_row + 64) * KPAD + l_sg) * 2);
    const size_t l_ga0 = (size_t)(bm + l_row) * Kd + l_sg;
    const size_t l_ga2 = (size_t)(bm + l_row + 64) * Kd + l_sg;
    const size_t l_gb0 = (size_t)(bn + l_row) * Kd + l_sg;
    const size_t l_gb2 = (size_t)(bn + l_row + 64) * Kd + l_sg;

    auto issue = [&](int c) {
        const uint32_t sb = sbase + (uint32_t)((c % 3) * STGB);
        const int k0 = c << 5;
        CP16(sb + l_so,       A  + l_ga0 + k0);
        CP16(sb + CB + l_so,  B1 + l_gb0 + k0);
        CP16(sb + l_so2,      A  + l_ga2 + k0);
        CP16(sb + CB + l_so2, B1 + l_gb2 + k0);
        CPCOMMIT();
    };

    issue(0);
    if (NC > 1) issue(1);

    const int lrow = lane & 15, lc8 = (lane >> 4) << 3;

    for (int c = 0; c < NC; c++) {
        if (c + 2 < NC) { issue(c + 2); CPWAIT(2); }
        else if (c + 1 < NC) { CPWAIT(1); }
        else { CPWAIT(0); }
        __syncthreads();

        const uint32_t sb = sbase + (uint32_t)((c % 3) * STGB);
#pragma unroll
        for (int ks = 0; ks < 2; ks++) {
            const int kf = ks * 16 + lc8;
            uint32_t bh[2][4];
#pragma unroll
            for (int ng = 0; ng < 2; ng++) {
                const uint32_t ro = (uint32_t)(((wn + ng * 16 + lrow) * KPAD + kf) * 2);
                ldsm4(bh[ng], sb + CB + ro);
            }
#pragma unroll
            for (int mt = 0; mt < 4; mt++) {
                uint32_t ah[4];
                const uint32_t ro = (uint32_t)(((wm + mt * 16 + lrow) * KPAD + kf) * 2);
                ldsm4(ah, sb + ro);
#pragma unroll
                for (int ng = 0; ng < 2; ng++)
#pragma unroll
                    for (int j = 0; j < 2; j++)
                        hmma2(acc[mt][ng * 2 + j], ah, bh[ng][j], bh[ng][j + 2]);
            }
        }
        __syncthreads();
    }

    const int g = lane >> 2, t2 = (lane & 3) * 2;
#pragma unroll
    for (int mt = 0; mt < 4; mt++) {
        const int r0 = bm + wm + mt * 16 + g;
#pragma unroll
        for (int nt = 0; nt < 4; nt++) {
            const int cn = bn + wn + nt * 8 + t2;
            float2 v0, v1;
            v0.x = acc[mt][nt][0] + bias[cn];
            v0.y = acc[mt][nt][1] + bias[cn + 1];
            v1.x = acc[mt][nt][2] + bias[cn];
            v1.y = acc[mt][nt][3] + bias[cn + 1];
            if (relu) {
                v0.x = fmaxf(v0.x, 0.0f); v0.y = fmaxf(v0.y, 0.0f);
                v1.x = fmaxf(v1.x, 0.0f); v1.y = fmaxf(v1.y, 0.0f);
            }
            v0.x *= oscale; v0.y *= oscale; v1.x *= oscale; v1.y *= oscale;
            if (Cf) {
                *(float2*)&Cf[(size_t)r0 * N + cn]       = v0;
                *(float2*)&Cf[(size_t)(r0 + 8) * N + cn] = v1;
            }
            if (Ch) {
                *(uint32_t*)&Ch[(size_t)r0 * N + cn]       = pack_f16x2(v0.x, v0.y);
                *(uint32_t*)&Ch[(size_t)(r0 + 8) * N + cn] = pack_f16x2(v1.x, v1.y);
            }
        }
    }
}

__global__ __launch_bounds__(256, 2)
void gemm_f16(const fp16* __restrict__ A, const fp16* __restrict__ B1,
              const float* __restrict__ bias,
              float* Cf, fp16* Ch, int N, int Kd, int relu, float oscale)
{
    extern __shared__ char smc[];
    gemm_body(A, B1, bias, Cf, Ch, N, Kd, relu, oscale,
              blockIdx.y * 128, blockIdx.x * 128, smem_u32(smc));
}

// Fused Q/K/V projections: one launch, 3328 CTAs.
__global__ __launch_bounds__(256, 2)
void qkv_f16(const fp16* __restrict__ t1, const fp16* __restrict__ i1,
             const fp16* __restrict__ wq, const fp16* __restrict__ wk,
             const fp16* __restrict__ wv,
             const float* __restrict__ bq, const float* __restrict__ bk,
             const float* __restrict__ bv,
             fp16* __restrict__ Q1, fp16* __restrict__ K1, fp16* __restrict__ V1)
{
    extern __shared__ char smc[];
    const int gid = blockIdx.x;
    const fp16 *A, *Bw;
    const float* bias;
    fp16* C;
    int Kd, loc;
    float osc;
    if (gid < 1024)      { loc = gid;        A = t1; Bw = wq; bias = bq; C = Q1; Kd = TD; osc = 0.0625f; }
    else if (gid < 2176) { loc = gid - 1024; A = i1; Bw = wk; bias = bk; C = K1; Kd = ID; osc = 1.0f; }
    else                 { loc = gid - 2176; A = i1; Bw = wv; bias = bv; C = V1; Kd = ID; osc = 1.0f; }
    const int bn = (loc & 15) * 128;
    const int bm = (loc >> 4) * 128;
    gemm_body(A, Bw, bias, nullptr, C, HID, Kd, 0, osc, bm, bn, smem_u32(smc));
}

// ===========================================================================
// fp16 flash attention (R10/R13 config): 256 threads, q-tile 128, kv-tile 64,
// cp.async double-buffered K/V, 9 iterations.
// ===========================================================================
#define ASD 264
#define KVB (64 * ASD * 2)
#define ASMEM_BYTES (128 * ASD * 2 + 4 * KVB)

__global__ __launch_bounds__(256, 1)
void attn2(const fp16* __restrict__ Q1, const fp16* __restrict__ K1,
           const fp16* __restrict__ V1, fp16* __restrict__ X1)
{
    extern __shared__ fp16 sm2[];
    fp16* sQ = sm2;
    const uint32_t sQb = smem_u32(sm2);
    const uint32_t sK0 = sQb + 128 * ASD * 2;
    const uint32_t sV0 = sK0 + 2 * KVB;

    const int tid  = threadIdx.x;
    const int wid  = tid >> 5;
    const int lane = tid & 31;
    const int qt = blockIdx.x, h = blockIdx.y, b = blockIdx.z;
    const int qrow0  = b * LT + qt * 128;
    const int kvrow0 = b * LI;
    const int hcol   = h * HD;

#pragma unroll
    for (int i = 0; i < 16; i++) {
        const int gi = tid + i * 256;
        const int r = gi >> 5, c8 = (gi & 31) << 3;
        *(float4*)&sQ[r * ASD + c8] =
            *(const float4*)&Q1[(size_t)(qrow0 + r) * HID + hcol + c8];
    }

    const int lrow = lane & 15, lc8 = (lane >> 4) << 3;
    const uint32_t aQ = sQb + (uint32_t)(((wid * 16 + lrow) * ASD + lc8) * 2);
    const uint32_t fro = (uint32_t)((lrow * ASD + lc8) * 2);

    auto issue_kv = [&](int st) {
        const uint32_t kb = sK0 + (uint32_t)((st & 1) * KVB);
        const uint32_t vb = sV0 + (uint32_t)((st & 1) * KVB);
#pragma unroll
        for (int i = 0; i < 8; i++) {
            const int gi = tid + i * 256;
            const int r = gi >> 5, c8 = (gi & 31) << 3;
            const uint32_t so = (uint32_t)((r * ASD + c8) * 2);
            const size_t ga = (size_t)(kvrow0 + st * 64 + r) * HID + hcol + c8;
            CP16(kb + so, K1 + ga);
            CP16(vb + so, V1 + ga);
        }
        CPCOMMIT();
    };

    float o[32][4];
#pragma unroll
    for (int i = 0; i < 32; i++)
#pragma unroll
        for (int j = 0; j < 4; j++) o[i][j] = 0.0f;
    float m0 = -1e30f, m1 = -1e30f, l0 = 0.0f, l1 = 0.0f;

    issue_kv(0);

    for (int st = 0; st < 9; st++) {
        if (st + 1 < 9) { issue_kv(st + 1); CPWAIT(1); } else { CPWAIT(0); }
        __syncthreads();

        const uint32_t aK = sK0 + (uint32_t)((st & 1) * KVB) + fro;
        const uint32_t aV = sV0 + (uint32_t)((st & 1) * KVB) + fro;

        float s[8][4];
#pragma unroll
        for (int i = 0; i < 8; i++)
#pragma unroll
            for (int j = 0; j < 4; j++) s[i][j] = 0.0f;

#pragma unroll
        for (int dc = 0; dc < 16; dc++) {
            uint32_t q0[4];
            ldsm4(q0, aQ + dc * 32);
#pragma unroll
            for (int kg = 0; kg < 4; kg++) {
                uint32_t k0[4];
                ldsm4(k0, aK + (uint32_t)(kg * 16 * ASD * 2) + dc * 32);
                hmma2(s[2 * kg],     q0, k0[0], k0[2]);
                hmma2(s[2 * kg + 1], q0, k0[1], k0[3]);
            }
        }

        float rm0 = s[0][0], rm1 = s[0][2];
#pragma unroll
        for (int nt = 0; nt < 8; nt++) {
            rm0 = fmaxf(rm0, fmaxf(s[nt][0], s[nt][1]));
            rm1 = fmaxf(rm1, fmaxf(s[nt][2], s[nt][3]));
        }
        rm0 = fmaxf(rm0, __shfl_xor_sync(0xffffffffu, rm0, 1));
        rm0 = fmaxf(rm0, __shfl_xor_sync(0xffffffffu, rm0, 2));
        rm1 = fmaxf(rm1, __shfl_xor_sync(0xffffffffu, rm1, 1));
        rm1 = fmaxf(rm1, __shfl_xor_sync(0xffffffffu, rm1, 2));
        const float nm0 = fmaxf(m0, rm0), nm1 = fmaxf(m1, rm1);
        const float sc0 = __expf(m0 - nm0), sc1 = __expf(m1 - nm1);
        m0 = nm0; m1 = nm1;
        float ps0 = 0.0f, ps1 = 0.0f;
#pragma unroll
        for (int nt = 0; nt < 8; nt++) {
            s[nt][0] = __expf(s[nt][0] - nm0); ps0 += s[nt][0];
            s[nt][1] = __expf(s[nt][1] - nm0); ps0 += s[nt][1];
            s[nt][2] = __expf(s[nt][2] - nm1); ps1 += s[nt][2];
            s[nt][3] = __expf(s[nt][3] - nm1); ps1 += s[nt][3];
        }
        ps0 += __shfl_xor_sync(0xffffffffu, ps0, 1);
        ps0 += __shfl_xor_sync(0xffffffffu, ps0, 2);
        ps1 += __shfl_xor_sync(0xffffffffu, ps1, 1);
        ps1 += __shfl_xor_sync(0xffffffffu, ps1, 2);
        l0 = l0 * sc0 + ps0;
        l1 = l1 * sc1 + ps1;

#pragma unroll
        for (int nt = 0; nt < 32; nt++) {
            o[nt][0] *= sc0; o[nt][1] *= sc0;
            o[nt][2] *= sc1; o[nt][3] *= sc1;
        }

        uint32_t pa[4][4];
#pragma unroll
        for (int kc = 0; kc < 4; kc++) {
            const float* f0 = s[2 * kc];
            const float* f1 = s[2 * kc + 1];
            pa[kc][0] = pack_f16x2(f0[0], f0[1]);
            pa[kc][1] = pack_f16x2(f0[2], f0[3]);
            pa[kc][2] = pack_f16x2(f1[0], f1[1]);
            pa[kc][3] = pack_f16x2(f1[2], f1[3]);
        }

#pragma unroll
        for (int kc = 0; kc < 4; kc++) {
            const uint32_t vbase = (uint32_t)(kc * 16 * ASD * 2);
#pragma unroll
            for (int nd = 0; nd < 16; nd++) {
                uint32_t vh[4];
                ldsm4t(vh, aV + vbase + nd * 32);
                hmma2(o[2 * nd],     pa[kc], vh[0], vh[1]);
                hmma2(o[2 * nd + 1], pa[kc], vh[2], vh[3]);
            }
        }
        __syncthreads();
    }

    const float i0 = 1.0f / l0, i1 = 1.0f / l1;
    const int g = lane >> 2, t2 = (lane & 3) * 2;
    const int r0 = qrow0 + wid * 16 + g;
#pragma unroll
    for (int nt = 0; nt < 32; nt++) {
        const int col = hcol + nt * 8 + t2;
        *(uint32_t*)&X1[(size_t)r0 * HID + col] =
            pack_f16x2(o[nt][0] * i0, o[nt][1] * i0);
        *(uint32_t*)&X1[(size_t)(r0 + 8) * HID + col] =
            pack_f16x2(o[nt][2] * i1, o[nt][3] * i1);
    }
}

// ---------------------------------------------------------------------------
// Residual + LayerNorm epilogue
// ---------------------------------------------------------------------------
__device__ __forceinline__ float block_sum(float x, float* red)
{
#pragma unroll
    for (int off = 16; off > 0; off >>= 1)
        x += __shfl_xor_sync(0xffffffffu, x, off);
    const int w = threadIdx.x >> 5;
    if ((threadIdx.x & 31) == 0) red[w] = x;
    __syncthreads();
    if (threadIdx.x < 32) {
        float y = (threadIdx.x < 8) ? red[threadIdx.x] : 0.0f;
#pragma unroll
        for (int off = 4; off > 0; off >>= 1)
            y += __shfl_xor_sync(0xffffffffu, y, off);
        if (threadIdx.x == 0) red[0] = y;
    }
    __syncthreads();
    const float r = red[0];
    __syncthreads();
    return r;
}

__global__ __launch_bounds__(256)
void ffln_kernel(const float* __restrict__ OUT, const float* __restrict__ FF,
                 const float* __restrict__ gamma, const float* __restrict__ beta,
                 float* __restrict__ Y)
{
    __shared__ float red[8];
    const int r = blockIdx.x;
    const int tid = threadIdx.x;
    float v[3];
#pragma unroll
    for (int i = 0; i < 3; i++) {
        const int idx = tid + i * 256;
        v[i] = OUT[(size_t)r * TD + idx] + FF[(size_t)r * TD + idx];
    }
    const float mu = block_sum(v[0] + v[1] + v[2], red) * (1.0f / 768.0f);
    const float d0 = v[0] - mu, d1 = v[1] - mu, d2 = v[2] - mu;
    const float var = block_sum(d0 * d0 + d1 * d1 + d2 * d2, red) * (1.0f / 768.0f);
    const float rstd = rsqrtf(var + 1e-5f);
#pragma unroll
    for (int i = 0; i < 3; i++) {
        const int idx = tid + i * 256;
        Y[(size_t)r * TD + idx] = (v[i] - mu) * rstd * gamma[idx] + beta[idx];
    }
}

// ---------------------------------------------------------------------------
extern "C" void kernel_launch(void* const* d_in, const int* in_sizes, int n_in,
                              void* d_out, int out_size)
{
    const float* text  = (const float*)d_in[0];
    const float* image = (const float*)d_in[1];
    const float* wq = (const float*)d_in[2];
    const float* bq = (const float*)d_in[3];
    const float* wk = (const float*)d_in[4];
    const float* bk = (const float*)d_in[5];
    const float* wv = (const float*)d_in[6];
    const float* bv = (const float*)d_in[7];
    const float* wr = (const float*)d_in[8];
    const float* br = (const float*)d_in[9];
    const float* w1 = (const float*)d_in[10];
    const float* b1 = (const float*)d_in[11];
    const float* w2 = (const float*)d_in[12];
    const float* b2 = (const float*)d_in[13];
    const float* gamma = (const float*)d_in[14];
    const float* beta  = (const float*)d_in[15];
    float* Y = (float*)d_out;

    fp16 *t1, *i1, *pwq, *pwk, *pwv, *pwr, *pw1, *pw2;
    fp16 *Q1, *K1, *V1, *X1, *O1, *H1;
    float *O, *F;
    cudaGetSymbolAddress((void**)&t1, g_t1);
    cudaGetSymbolAddress((void**)&i1, g_i1);
    cudaGetSymbolAddress((void**)&pwq, g_wq);  cudaGetSymbolAddress((void**)&pwk, g_wk);
    cudaGetSymbolAddress((void**)&pwv, g_wv);  cudaGetSymbolAddress((void**)&pwr, g_wr);
    cudaGetSymbolAddress((void**)&pw1, g_w1);  cudaGetSymbolAddress((void**)&pw2, g_w2);
    cudaGetSymbolAddress((void**)&Q1, g_Q1);   cudaGetSymbolAddress((void**)&K1, g_K1);
    cudaGetSymbolAddress((void**)&V1, g_V1);   cudaGetSymbolAddress((void**)&X1, g_X1);
    cudaGetSymbolAddress((void**)&O1, g_O1);   cudaGetSymbolAddress((void**)&H1, g_H1);
    cudaGetSymbolAddress((void**)&O, g_O);
    cudaGetSymbolAddress((void**)&F, g_F);

    cudaFuncSetAttribute(gemm_f16, cudaFuncAttributeMaxDynamicSharedMemorySize, GSMEM_BYTES);
    cudaFuncSetAttribute(qkv_f16,  cudaFuncAttributeMaxDynamicSharedMemorySize, GSMEM_BYTES);
    cudaFuncSetAttribute(attn2, cudaFuncAttributeMaxDynamicSharedMemorySize, ASMEM_BYTES);

    // --- fused pre-pass (1 launch) ---
    prep<<<PREP_GRID, 256>>>(text, image, wq, wk, wv, wr, w1, w2,
                             t1, i1, pwq, pwk, pwv, pwr, pw1, pw2);

    // --- fused Q/K/V projections (Q scaled by 1/sqrt(256)) ---
    qkv_f16<<<3328, 256, GSMEM_BYTES>>>(t1, i1, pwq, pwk, pwv, bq, bk, bv, Q1, K1, V1);

    // --- attention ---
    attn2<<<dim3(LT / 128, NH, B_), 256, ASMEM_BYTES>>>(Q1, K1, V1, X1);

    // --- output projection + FF ---
    gemm_f16<<<dim3(TD / 128, (B_ * LT) / 128), 256, GSMEM_BYTES>>>(
        X1, pwr, br, O, O1, TD, HID, 0, 1.0f);
    gemm_f16<<<dim3(FFD / 128, (B_ * LT) / 128), 256, GSMEM_BYTES>>>(
        O1, pw1, b1, nullptr, H1, FFD, TD, 1, 1.0f);
    gemm_f16<<<dim3(TD / 128, (B_ * LT) / 128), 256, GSMEM_BYTES>>>(
        H1, pw2, b2, F, nullptr, TD, FFD, 0, 1.0f);

    // --- residual + LayerNorm ---
    ffln_kernel<<<B_ * LT, 256>>>(O, F, gamma, beta, Y);
}

// round 15
// speedup vs baseline: 1.5277x; 1.0824x over previous
#include <cuda_runtime.h>
#include <cuda_fp16.h>
#include <cstdint>
#include <math.h>

#define B_   16
#define LT   512
#define LI   576
#define TD   768
#define ID   1024
#define HID  2048
#define NH   8
#define HD   256
#define FFD  128

typedef __half fp16;

// ---- scratch (device globals) ----
__device__ fp16 g_t1[B_ * LT * TD];
__device__ fp16 g_i1[B_ * LI * ID];
__device__ fp16 g_wq[HID * TD];
__device__ fp16 g_wk[HID * ID];
__device__ fp16 g_wv[HID * ID];
__device__ fp16 g_wr[TD * HID];
__device__ fp16 g_w1[FFD * TD];
__device__ fp16 g_w2[TD * FFD];
__device__ fp16 g_Q1[B_ * LT * HID];
__device__ fp16 g_K1[B_ * LI * HID];
__device__ fp16 g_V1[B_ * LI * HID];
__device__ fp16 g_X1[B_ * LT * HID];
__device__ fp16 g_O1[B_ * LT * TD];
__device__ fp16 g_H1[B_ * LT * FFD];
__device__ float g_O[B_ * LT * TD];
__device__ float g_F[B_ * LT * TD];

// ===========================================================================
// helpers
// ===========================================================================
__device__ __forceinline__ void hmma2(float* c, const uint32_t* a, uint32_t b0, uint32_t b1)
{
    asm volatile(
        "mma.sync.aligned.m16n8k16.row.col.f32.f16.f16.f32 "
        "{%0,%1,%2,%3}, {%4,%5,%6,%7}, {%8,%9}, {%0,%1,%2,%3};"
        : "+f"(c[0]), "+f"(c[1]), "+f"(c[2]), "+f"(c[3])
        : "r"(a[0]), "r"(a[1]), "r"(a[2]), "r"(a[3]), "r"(b0), "r"(b1));
}
__device__ __forceinline__ void ldsm4(uint32_t* r, uint32_t addr)
{
    asm volatile("ldmatrix.sync.aligned.m8n8.x4.shared.b16 {%0,%1,%2,%3}, [%4];"
                 : "=r"(r[0]), "=r"(r[1]), "=r"(r[2]), "=r"(r[3]) : "r"(addr));
}
__device__ __forceinline__ void ldsm4t(uint32_t* r, uint32_t addr)
{
    asm volatile("ldmatrix.sync.aligned.m8n8.x4.trans.shared.b16 {%0,%1,%2,%3}, [%4];"
                 : "=r"(r[0]), "=r"(r[1]), "=r"(r[2]), "=r"(r[3]) : "r"(addr));
}
__device__ __forceinline__ uint32_t smem_u32(const void* p) {
    uint32_t a;
    asm("{ .reg .u64 t; cvta.to.shared.u64 t, %1; cvt.u32.u64 %0, t; }" : "=r"(a) : "l"(p));
    return a;
}
__device__ __forceinline__ uint32_t pack_f16x2(float x0, float x1)
{
    __half2 h = __floats2half2_rn(x0, x1);
    return *(uint32_t*)&h;
}
#define CP16(s, g) \
    asm volatile("cp.async.cg.shared.global [%0], [%1], 16;" :: "r"(s), "l"(g) : "memory")
#define CPCOMMIT() asm volatile("cp.async.commit_group;" ::: "memory")
#define CPWAIT(n)  asm volatile("cp.async.wait_group %0;" :: "n"(n) : "memory")

// ===========================================================================
// Fused pre-pass (one launch): activation fp32->fp16 + 6 weight transposes.
// ===========================================================================
#define PREP_GRID 22720

__device__ __forceinline__ void cvt_seg(const float* X, fp16* H, int loc)
{
    const int i = (loc * 256 + threadIdx.x) * 4;
    float4 v = *(const float4*)&X[i];
    *(uint32_t*)&H[i]     = pack_f16x2(v.x, v.y);
    *(uint32_t*)&H[i + 2] = pack_f16x2(v.z, v.w);
}
__device__ __forceinline__ void tr_seg(const float* W, fp16* T, int K, int N, int loc)
{
    __shared__ float t[32][33];
    const int nt = loc % (N >> 5), kt = loc / (N >> 5);
    const int n0 = nt * 32, k0 = kt * 32;
    const int tx = threadIdx.x & 31, ty4 = (threadIdx.x >> 5) * 4;
#pragma unroll
    for (int i = 0; i < 4; i++)
        t[ty4 + i][tx] = W[(size_t)(k0 + ty4 + i) * N + n0 + tx];
    __syncthreads();
#pragma unroll
    for (int i = 0; i < 4; i++)
        T[(size_t)(n0 + ty4 + i) * K + k0 + tx] = __float2half_rn(t[tx][ty4 + i]);
}

__global__ __launch_bounds__(256)
void prep(const float* __restrict__ text, const float* __restrict__ image,
          const float* __restrict__ wq, const float* __restrict__ wk,
          const float* __restrict__ wv, const float* __restrict__ wr,
          const float* __restrict__ w1, const float* __restrict__ w2,
          fp16* t1, fp16* i1, fp16* pwq, fp16* pwk, fp16* pwv,
          fp16* pwr, fp16* pw1, fp16* pw2)
{
    const int g = blockIdx.x;
    if      (g < 6144)  cvt_seg(text,  t1, g);
    else if (g < 15360) cvt_seg(image, i1, g - 6144);
    else if (g < 16896) tr_seg(wq, pwq, TD,  HID, g - 15360);
    else if (g < 18944) tr_seg(wk, pwk, ID,  HID, g - 16896);
    else if (g < 20992) tr_seg(wv, pwv, ID,  HID, g - 18944);
    else if (g < 22528) tr_seg(wr, pwr, HID, TD,  g - 20992);
    else if (g < 22624) tr_seg(w1, pw1, TD,  FFD, g - 22528);
    else                tr_seg(w2, pw2, FFD, TD,  g - 22624);
}

// ===========================================================================
// fp16 GEMM body: C = A[M,K] @ B1[N,K]^T + bias
// 128x128 block, BK=32, 4-stage cp.async, lookahead-2, ONE barrier/chunk,
// 2 CTAs/SM.
// Hazard proof: issue(c+2) writes stage (c+2)&3 == (c-2)&3. All threads
// passing iteration (c-1)'s barrier have finished compute of chunk c-2,
// so the overwrite is safe without a bottom barrier.
// ===========================================================================
#define KPAD 40
#define CB   (128 * KPAD * 2)
#define STGB (2 * CB)
#define GSMEM_BYTES (4 * STGB)    // 81920 (<=114KB -> 2 CTAs/SM)

__device__ __forceinline__ void gemm_body(
    const fp16* __restrict__ A, const fp16* __restrict__ B1,
    const float* __restrict__ bias,
    float* Cf, fp16* Ch,
    int N, int Kd, int relu, float oscale,
    int bm, int bn, uint32_t sbase)
{
    const int tid  = threadIdx.x;
    const int wid  = tid >> 5;
    const int lane = tid & 31;
    const int wm = (wid >> 2) * 64;
    const int wn = (wid & 3) * 32;
    const int NC = Kd >> 5;

    float acc[4][4][4];
#pragma unroll
    for (int i = 0; i < 4; i++)
#pragma unroll
        for (int j = 0; j < 4; j++)
#pragma unroll
            for (int l = 0; l < 4; l++) acc[i][j][l] = 0.0f;

    const int l_row = tid >> 2, l_sg = (tid & 3) << 3;
    const uint32_t l_so  = (uint32_t)((l_row * KPAD + l_sg) * 2);
    const uint32_t l_so2 = (uint32_t)(((l_row + 64) * KPAD + l_sg) * 2);
    const size_t l_ga0 = (size_t)(bm + l_row) * Kd + l_sg;
    const size_t l_ga2 = (size_t)(bm + l_row + 64) * Kd + l_sg;
    const size_t l_gb0 = (size_t)(bn + l_row) * Kd + l_sg;
    const size_t l_gb2 = (size_t)(bn + l_row + 64) * Kd + l_sg;

    auto issue = [&](int c) {
        const uint32_t sb = sbase + (uint32_t)((c & 3) * STGB);
        const int k0 = c << 5;
        CP16(sb + l_so,       A  + l_ga0 + k0);
        CP16(sb + CB + l_so,  B1 + l_gb0 + k0);
        CP16(sb + l_so2,      A  + l_ga2 + k0);
        CP16(sb + CB + l_so2, B1 + l_gb2 + k0);
        CPCOMMIT();
    };

    issue(0);
    if (NC > 1) issue(1);

    const int lrow = lane & 15, lc8 = (lane >> 4) << 3;

    for (int c = 0; c < NC; c++) {
        if (c + 2 < NC) { issue(c + 2); CPWAIT(2); }
        else if (c + 1 < NC) { CPWAIT(1); }
        else { CPWAIT(0); }
        __syncthreads();    // publish chunk c; also fences stage reuse (see proof)

        const uint32_t sb = sbase + (uint32_t)((c & 3) * STGB);
#pragma unroll
        for (int ks = 0; ks < 2; ks++) {
            const int kf = ks * 16 + lc8;
            uint32_t bh[2][4];
#pragma unroll
            for (int ng = 0; ng < 2; ng++) {
                const uint32_t ro = (uint32_t)(((wn + ng * 16 + lrow) * KPAD + kf) * 2);
                ldsm4(bh[ng], sb + CB + ro);
            }
#pragma unroll
            for (int mt = 0; mt < 4; mt++) {
                uint32_t ah[4];
                const uint32_t ro = (uint32_t)(((wm + mt * 16 + lrow) * KPAD + kf) * 2);
                ldsm4(ah, sb + ro);
#pragma unroll
                for (int ng = 0; ng < 2; ng++)
#pragma unroll
                    for (int j = 0; j < 2; j++)
                        hmma2(acc[mt][ng * 2 + j], ah, bh[ng][j], bh[ng][j + 2]);
            }
        }
    }

    const int g = lane >> 2, t2 = (lane & 3) * 2;
#pragma unroll
    for (int mt = 0; mt < 4; mt++) {
        const int r0 = bm + wm + mt * 16 + g;
#pragma unroll
        for (int nt = 0; nt < 4; nt++) {
            const int cn = bn + wn + nt * 8 + t2;
            float2 v0, v1;
            v0.x = acc[mt][nt][0] + bias[cn];
            v0.y = acc[mt][nt][1] + bias[cn + 1];
            v1.x = acc[mt][nt][2] + bias[cn];
            v1.y = acc[mt][nt][3] + bias[cn + 1];
            if (relu) {
                v0.x = fmaxf(v0.x, 0.0f); v0.y = fmaxf(v0.y, 0.0f);
                v1.x = fmaxf(v1.x, 0.0f); v1.y = fmaxf(v1.y, 0.0f);
            }
            v0.x *= oscale; v0.y *= oscale; v1.x *= oscale; v1.y *= oscale;
            if (Cf) {
                *(float2*)&Cf[(size_t)r0 * N + cn]       = v0;
                *(float2*)&Cf[(size_t)(r0 + 8) * N + cn] = v1;
            }
            if (Ch) {
                *(uint32_t*)&Ch[(size_t)r0 * N + cn]       = pack_f16x2(v0.x, v0.y);
                *(uint32_t*)&Ch[(size_t)(r0 + 8) * N + cn] = pack_f16x2(v1.x, v1.y);
            }
        }
    }
}

__global__ __launch_bounds__(256, 2)
void gemm_f16(const fp16* __restrict__ A, const fp16* __restrict__ B1,
              const float* __restrict__ bias,
              float* Cf, fp16* Ch, int N, int Kd, int relu, float oscale)
{
    extern __shared__ char smc[];
    gemm_body(A, B1, bias, Cf, Ch, N, Kd, relu, oscale,
              blockIdx.y * 128, blockIdx.x * 128, smem_u32(smc));
}

// Fused Q/K/V projections: one launch, 3328 CTAs.
__global__ __launch_bounds__(256, 2)
void qkv_f16(const fp16* __restrict__ t1, const fp16* __restrict__ i1,
             const fp16* __restrict__ wq, const fp16* __restrict__ wk,
             const fp16* __restrict__ wv,
             const float* __restrict__ bq, const float* __restrict__ bk,
             const float* __restrict__ bv,
             fp16* __restrict__ Q1, fp16* __restrict__ K1, fp16* __restrict__ V1)
{
    extern __shared__ char smc[];
    const int gid = blockIdx.x;
    const fp16 *A, *Bw;
    const float* bias;
    fp16* C;
    int Kd, loc;
    float osc;
    if (gid < 1024)      { loc = gid;        A = t1; Bw = wq; bias = bq; C = Q1; Kd = TD; osc = 0.0625f; }
    else if (gid < 2176) { loc = gid - 1024; A = i1; Bw = wk; bias = bk; C = K1; Kd = ID; osc = 1.0f; }
    else                 { loc = gid - 2176; A = i1; Bw = wv; bias = bv; C = V1; Kd = ID; osc = 1.0f; }
    const int bn = (loc & 15) * 128;
    const int bm = (loc >> 4) * 128;
    gemm_body(A, Bw, bias, nullptr, C, HID, Kd, 0, osc, bm, bn, smem_u32(smc));
}

// ===========================================================================
// fp16 flash attention: 256 threads, q-tile 128, kv-tile 64,
// cp.async double-buffered K/V, 9 iterations. (R14 config, unchanged.)
// ===========================================================================
#define ASD 264
#define KVB (64 * ASD * 2)
#define ASMEM_BYTES (128 * ASD * 2 + 4 * KVB)

__global__ __launch_bounds__(256, 1)
void attn2(const fp16* __restrict__ Q1, const fp16* __restrict__ K1,
           const fp16* __restrict__ V1, fp16* __restrict__ X1)
{
    extern __shared__ fp16 sm2[];
    fp16* sQ = sm2;
    const uint32_t sQb = smem_u32(sm2);
    const uint32_t sK0 = sQb + 128 * ASD * 2;
    const uint32_t sV0 = sK0 + 2 * KVB;

    const int tid  = threadIdx.x;
    const int wid  = tid >> 5;
    const int lane = tid & 31;
    const int qt = blockIdx.x, h = blockIdx.y, b = blockIdx.z;
    const int qrow0  = b * LT + qt * 128;
    const int kvrow0 = b * LI;
    const int hcol   = h * HD;

#pragma unroll
    for (int i = 0; i < 16; i++) {
        const int gi = tid + i * 256;
        const int r = gi >> 5, c8 = (gi & 31) << 3;
        *(float4*)&sQ[r * ASD + c8] =
            *(const float4*)&Q1[(size_t)(qrow0 + r) * HID + hcol + c8];
    }

    const int lrow = lane & 15, lc8 = (lane >> 4) << 3;
    const uint32_t aQ = sQb + (uint32_t)(((wid * 16 + lrow) * ASD + lc8) * 2);
    const uint32_t fro = (uint32_t)((lrow * ASD + lc8) * 2);

    auto issue_kv = [&](int st) {
        const uint32_t kb = sK0 + (uint32_t)((st & 1) * KVB);
        const uint32_t vb = sV0 + (uint32_t)((st & 1) * KVB);
#pragma unroll
        for (int i = 0; i < 8; i++) {
            const int gi = tid + i * 256;
            const int r = gi >> 5, c8 = (gi & 31) << 3;
            const uint32_t so = (uint32_t)((r * ASD + c8) * 2);
            const size_t ga = (size_t)(kvrow0 + st * 64 + r) * HID + hcol + c8;
            CP16(kb + so, K1 + ga);
            CP16(vb + so, V1 + ga);
        }
        CPCOMMIT();
    };

    float o[32][4];
#pragma unroll
    for (int i = 0; i < 32; i++)
#pragma unroll
        for (int j = 0; j < 4; j++) o[i][j] = 0.0f;
    float m0 = -1e30f, m1 = -1e30f, l0 = 0.0f, l1 = 0.0f;

    issue_kv(0);

    for (int st = 0; st < 9; st++) {
        if (st + 1 < 9) { issue_kv(st + 1); CPWAIT(1); } else { CPWAIT(0); }
        __syncthreads();

        const uint32_t aK = sK0 + (uint32_t)((st & 1) * KVB) + fro;
        const uint32_t aV = sV0 + (uint32_t)((st & 1) * KVB) + fro;

        float s[8][4];
#pragma unroll
        for (int i = 0; i < 8; i++)
#pragma unroll
            for (int j = 0; j < 4; j++) s[i][j] = 0.0f;

#pragma unroll
        for (int dc = 0; dc < 16; dc++) {
            uint32_t q0[4];
            ldsm4(q0, aQ + dc * 32);
#pragma unroll
            for (int kg = 0; kg < 4; kg++) {
                uint32_t k0[4];
                ldsm4(k0, aK + (uint32_t)(kg * 16 * ASD * 2) + dc * 32);
                hmma2(s[2 * kg],     q0, k0[0], k0[2]);
                hmma2(s[2 * kg + 1], q0, k0[1], k0[3]);
            }
        }

        float rm0 = s[0][0], rm1 = s[0][2];
#pragma unroll
        for (int nt = 0; nt < 8; nt++) {
            rm0 = fmaxf(rm0, fmaxf(s[nt][0], s[nt][1]));
            rm1 = fmaxf(rm1, fmaxf(s[nt][2], s[nt][3]));
        }
        rm0 = fmaxf(rm0, __shfl_xor_sync(0xffffffffu, rm0, 1));
        rm0 = fmaxf(rm0, __shfl_xor_sync(0xffffffffu, rm0, 2));
        rm1 = fmaxf(rm1, __shfl_xor_sync(0xffffffffu, rm1, 1));
        rm1 = fmaxf(rm1, __shfl_xor_sync(0xffffffffu, rm1, 2));
        const float nm0 = fmaxf(m0, rm0), nm1 = fmaxf(m1, rm1);
        const float sc0 = __expf(m0 - nm0), sc1 = __expf(m1 - nm1);
        m0 = nm0; m1 = nm1;
        float ps0 = 0.0f, ps1 = 0.0f;
#pragma unroll
        for (int nt = 0; nt < 8; nt++) {
            s[nt][0] = __expf(s[nt][0] - nm0); ps0 += s[nt][0];
            s[nt][1] = __expf(s[nt][1] - nm0); ps0 += s[nt][1];
            s[nt][2] = __expf(s[nt][2] - nm1); ps1 += s[nt][2];
            s[nt][3] = __expf(s[nt][3] - nm1); ps1 += s[nt][3];
        }
        ps0 += __shfl_xor_sync(0xffffffffu, ps0, 1);
        ps0 += __shfl_xor_sync(0xffffffffu, ps0, 2);
        ps1 += __shfl_xor_sync(0xffffffffu, ps1, 1);
        ps1 += __shfl_xor_sync(0xffffffffu, ps1, 2);
        l0 = l0 * sc0 + ps0;
        l1 = l1 * sc1 + ps1;

#pragma unroll
        for (int nt = 0; nt < 32; nt++) {
            o[nt][0] *= sc0; o[nt][1] *= sc0;
            o[nt][2] *= sc1; o[nt][3] *= sc1;
        }

        uint32_t pa[4][4];
#pragma unroll
        for (int kc = 0; kc < 4; kc++) {
            const float* f0 = s[2 * kc];
            const float* f1 = s[2 * kc + 1];
            pa[kc][0] = pack_f16x2(f0[0], f0[1]);
            pa[kc][1] = pack_f16x2(f0[2], f0[3]);
            pa[kc][2] = pack_f16x2(f1[0], f1[1]);
            pa[kc][3] = pack_f16x2(f1[2], f1[3]);
        }

#pragma unroll
        for (int kc = 0; kc < 4; kc++) {
            const uint32_t vbase = (uint32_t)(kc * 16 * ASD * 2);
#pragma unroll
            for (int nd = 0; nd < 16; nd++) {
                uint32_t vh[4];
                ldsm4t(vh, aV + vbase + nd * 32);
                hmma2(o[2 * nd],     pa[kc], vh[0], vh[1]);
                hmma2(o[2 * nd + 1], pa[kc], vh[2], vh[3]);
            }
        }
        __syncthreads();
    }

    const float i0 = 1.0f / l0, i1 = 1.0f / l1;
    const int g = lane >> 2, t2 = (lane & 3) * 2;
    const int r0 = qrow0 + wid * 16 + g;
#pragma unroll
    for (int nt = 0; nt < 32; nt++) {
        const int col = hcol + nt * 8 + t2;
        *(uint32_t*)&X1[(size_t)r0 * HID + col] =
            pack_f16x2(o[nt][0] * i0, o[nt][1] * i0);
        *(uint32_t*)&X1[(size_t)(r0 + 8) * HID + col] =
            pack_f16x2(o[nt][2] * i1, o[nt][3] * i1);
    }
}

// ---------------------------------------------------------------------------
// Residual + LayerNorm epilogue
// ---------------------------------------------------------------------------
__device__ __forceinline__ float block_sum(float x, float* red)
{
#pragma unroll
    for (int off = 16; off > 0; off >>= 1)
        x += __shfl_xor_sync(0xffffffffu, x, off);
    const int w = threadIdx.x >> 5;
    if ((threadIdx.x & 31) == 0) red[w] = x;
    __syncthreads();
    if (threadIdx.x < 32) {
        float y = (threadIdx.x < 8) ? red[threadIdx.x] : 0.0f;
#pragma unroll
        for (int off = 4; off > 0; off >>= 1)
            y += __shfl_xor_sync(0xffffffffu, y, off);
        if (threadIdx.x == 0) red[0] = y;
    }
    __syncthreads();
    const float r = red[0];
    __syncthreads();
    return r;
}

__global__ __launch_bounds__(256)
void ffln_kernel(const float* __restrict__ OUT, const float* __restrict__ FF,
                 const float* __restrict__ gamma, const float* __restrict__ beta,
                 float* __restrict__ Y)
{
    __shared__ float red[8];
    const int r = blockIdx.x;
    const int tid = threadIdx.x;
    float v[3];
#pragma unroll
    for (int i = 0; i < 3; i++) {
        const int idx = tid + i * 256;
        v[i] = OUT[(size_t)r * TD + idx] + FF[(size_t)r * TD + idx];
    }
    const float mu = block_sum(v[0] + v[1] + v[2], red) * (1.0f / 768.0f);
    const float d0 = v[0] - mu, d1 = v[1] - mu, d2 = v[2] - mu;
    const float var = block_sum(d0 * d0 + d1 * d1 + d2 * d2, red) * (1.0f / 768.0f);
    const float rstd = rsqrtf(var + 1e-5f);
#pragma unroll
    for (int i = 0; i < 3; i++) {
        const int idx = tid + i * 256;
        Y[(size_t)r * TD + idx] = (v[i] - mu) * rstd * gamma[idx] + beta[idx];
    }
}

// ---------------------------------------------------------------------------
extern "C" void kernel_launch(void* const* d_in, const int* in_sizes, int n_in,
                              void* d_out, int out_size)
{
    const float* text  = (const float*)d_in[0];
    const float* image = (const float*)d_in[1];
    const float* wq = (const float*)d_in[2];
    const float* bq = (const float*)d_in[3];
    const float* wk = (const float*)d_in[4];
    const float* bk = (const float*)d_in[5];
    const float* wv = (const float*)d_in[6];
    const float* bv = (const float*)d_in[7];
    const float* wr = (const float*)d_in[8];
    const float* br = (const float*)d_in[9];
    const float* w1 = (const float*)d_in[10];
    const float* b1 = (const float*)d_in[11];
    const float* w2 = (const float*)d_in[12];
    const float* b2 = (const float*)d_in[13];
    const float* gamma = (const float*)d_in[14];
    const float* beta  = (const float*)d_in[15];
    float* Y = (float*)d_out;

    fp16 *t1, *i1, *pwq, *pwk, *pwv, *pwr, *pw1, *pw2;
    fp16 *Q1, *K1, *V1, *X1, *O1, *H1;
    float *O, *F;
    cudaGetSymbolAddress((void**)&t1, g_t1);
    cudaGetSymbolAddress((void**)&i1, g_i1);
    cudaGetSymbolAddress((void**)&pwq, g_wq);  cudaGetSymbolAddress((void**)&pwk, g_wk);
    cudaGetSymbolAddress((void**)&pwv, g_wv);  cudaGetSymbolAddress((void**)&pwr, g_wr);
    cudaGetSymbolAddress((void**)&pw1, g_w1);  cudaGetSymbolAddress((void**)&pw2, g_w2);
    cudaGetSymbolAddress((void**)&Q1, g_Q1);   cudaGetSymbolAddress((void**)&K1, g_K1);
    cudaGetSymbolAddress((void**)&V1, g_V1);   cudaGetSymbolAddress((void**)&X1, g_X1);
    cudaGetSymbolAddress((void**)&O1, g_O1);   cudaGetSymbolAddress((void**)&H1, g_H1);
    cudaGetSymbolAddress((void**)&O, g_O);
    cudaGetSymbolAddress((void**)&F, g_F);

    cudaFuncSetAttribute(gemm_f16, cudaFuncAttributeMaxDynamicSharedMemorySize, GSMEM_BYTES);
    cudaFuncSetAttribute(qkv_f16,  cudaFuncAttributeMaxDynamicSharedMemorySize, GSMEM_BYTES);
    cudaFuncSetAttribute(attn2, cudaFuncAttributeMaxDynamicSharedMemorySize, ASMEM_BYTES);

    // --- fused pre-pass (1 launch) ---
    prep<<<PREP_GRID, 256>>>(text, image, wq, wk, wv, wr, w1, w2,
                             t1, i1, pwq, pwk, pwv, pwr, pw1, pw2);

    // --- fused Q/K/V projections (Q scaled by 1/sqrt(256)) ---
    qkv_f16<<<3328, 256, GSMEM_BYTES>>>(t1, i1, pwq, pwk, pwv, bq, bk, bv, Q1, K1, V1);

    // --- attention ---
    attn2<<<dim3(LT / 128, NH, B_), 256, ASMEM_BYTES>>>(Q1, K1, V1, X1);

    // --- output projection + FF ---
    gemm_f16<<<dim3(TD / 128, (B_ * LT) / 128), 256, GSMEM_BYTES>>>(
        X1, pwr, br, O, O1, TD, HID, 0, 1.0f);
    gemm_f16<<<dim3(FFD / 128, (B_ * LT) / 128), 256, GSMEM_BYTES>>>(
        O1, pw1, b1, nullptr, H1, FFD, TD, 1, 1.0f);
    gemm_f16<<<dim3(TD / 128, (B_ * LT) / 128), 256, GSMEM_BYTES>>>(
        H1, pw2, b2, F, nullptr, TD, FFD, 0, 1.0f);

    // --- residual + LayerNorm ---
    ffln_kernel<<<B_ * LT, 256>>>(O, F, gamma, beta, Y);
}